// round 11
// baseline (speedup 1.0000x reference)
#include <cuda_runtime.h>
#include <math.h>
#include <stdint.h>

#define NN 50000
#define EE 800000
#define HD 128
#define GG 64

// ---------------- scratch (device globals: allocation-free) ----------------
__device__ float g_z[NN * HD];
__device__ float g_h[NN * HD];
__device__ float g_dinv[NN];
__device__ int   g_degi[NN];
__device__ int   g_rowptr[NN + 1];
__device__ int   g_cursor[NN];
__device__ int   g_col[EE];
__device__ int   g_bsum[64];
__device__ float g_f[GG * HD];
__device__ float g_t1[GG * 1024];
__device__ float g_t2[GG * 512];
__device__ float g_t3[GG * 256];
__device__ float g_t4[GG * HD];
__device__ float g_wT[3 * HD * HD];   // W^T, tf32-rounded

// ---------------- helpers ----------------
__device__ __forceinline__ float tf32_rna(float x) {
    uint32_t r; asm("cvt.rna.tf32.f32 %0, %1;" : "=r"(r) : "f"(x));
    return __uint_as_float(r);
}
__device__ __forceinline__ void mma_tf32(float* c, const uint32_t* a, const uint32_t* b) {
    asm volatile(
        "mma.sync.aligned.m16n8k8.row.col.f32.tf32.tf32.f32 "
        "{%0,%1,%2,%3}, {%4,%5,%6,%7}, {%8,%9}, {%0,%1,%2,%3};"
        : "+f"(c[0]), "+f"(c[1]), "+f"(c[2]), "+f"(c[3])
        : "r"(a[0]), "r"(a[1]), "r"(a[2]), "r"(a[3]), "r"(b[0]), "r"(b[1]));
}
#define CP16(dst_u32, src) \
    asm volatile("cp.async.cg.shared.global [%0], [%1], 16;" :: "r"(dst_u32), "l"(src))
#define CP16P(dst_u32, src, nbytes) \
    asm volatile("cp.async.cg.shared.global [%0], [%1], 16, %2;" :: "r"(dst_u32), "l"(src), "r"(nbytes))
#define CP_COMMIT() asm volatile("cp.async.commit_group;" ::: "memory")
#define CP_WAIT1()  asm volatile("cp.async.wait_group 1;" ::: "memory")
#define CP_WAIT0()  asm volatile("cp.async.wait_group 0;" ::: "memory")

// ---------------- CSR build ----------------
__global__ void k_count(const int* __restrict__ ei) {
    int e = blockIdx.x * blockDim.x + threadIdx.x;
    if (e < EE) atomicAdd(&g_degi[ei[EE + e]], 1);
}
__global__ void k_scan1() {
    __shared__ int s[1024];
    int t = threadIdx.x;
    int i = blockIdx.x * 1024 + t;
    int v = (i < NN) ? g_degi[i] : 0;
    s[t] = v;
    __syncthreads();
    for (int off = 1; off < 1024; off <<= 1) {
        int x = (t >= off) ? s[t - off] : 0;
        __syncthreads();
        s[t] += x;
        __syncthreads();
    }
    if (i < NN) g_rowptr[i] = s[t] - v;
    if (t == 1023) g_bsum[blockIdx.x] = s[1023];
}
__global__ void k_scan3(int nb) {
    __shared__ int sb[64];
    __shared__ int off_s;
    int t = threadIdx.x;
    if (t < nb) sb[t] = g_bsum[t];
    __syncthreads();
    if (t == 0) {
        int s = 0;
        for (int i = 0; i < blockIdx.x; i++) s += sb[i];
        off_s = s;
    }
    __syncthreads();
    int i = blockIdx.x * 1024 + t;
    if (i < NN) {
        int rp = g_rowptr[i] + off_s;
        g_rowptr[i] = rp;
        g_cursor[i] = rp;
        g_dinv[i]   = rsqrtf((float)(g_degi[i] + 1));
    }
    if (i == 0) g_rowptr[NN] = EE;
}
__global__ void k_fill(const int* __restrict__ ei) {
    int e = blockIdx.x * blockDim.x + threadIdx.x;
    if (e < EE) {
        int src = ei[e];
        int dst = ei[EE + e];
        int p = atomicAdd(&g_cursor[dst], 1);
        g_col[p] = src;
    }
}

// ---- weight prep: WT[n][k] = rna(W[k][n]) ----------------------------------
__global__ __launch_bounds__(256) void k_prep(const float* __restrict__ w1,
                                              const float* __restrict__ w2,
                                              const float* __restrict__ w3) {
    int layer = blockIdx.x >> 3;
    int part  = blockIdx.x & 7;
    const float* W = (layer == 0) ? w1 : ((layer == 1) ? w2 : w3);
    float* o = g_wT + layer * (HD * HD);
    for (int i = 0; i < 8; i++) {
        int idx = part * 2048 + i * 256 + threadIdx.x;   // 0..16383
        int k = idx >> 7;
        int n = idx & 127;
        o[n * HD + k] = tf32_rna(W[idx]);
    }
}

// ---------------- tf32 mma GEMM, BM=64 x BN=128, cp.async double-buffered --
// 128 threads, 4 warps (2m x 2n), warp tile 32x64 (same as before), BK=32.
#define APITCH 36
#define A_FLOATS (64 * APITCH)
#define B_FLOATS (128 * APITCH)
#define BUF_FLOATS (A_FLOATS + B_FLOATS)
#define SM_GEMM_FLOATS (2 * BUF_FLOATS)

__global__ __launch_bounds__(128, 4) void k_gemm_mma(const float* __restrict__ A,
                                                     const float* __restrict__ WT,
                                                     float* __restrict__ C,
                                                     int M, int scale, int around) {
    extern __shared__ float sm[];
    uint32_t sb_u32 = (uint32_t)__cvta_generic_to_shared(sm);
    int tid  = threadIdx.x;
    int wid  = tid >> 5;
    int lane = tid & 31;
    int g    = lane >> 2;
    int tig  = lane & 3;
    int wm   = wid & 1;      // 2 m-warps
    int wn   = wid >> 1;     // 2 n-warps
    int base = blockIdx.x * 64;

    float c[2][8][4];
    #pragma unroll
    for (int f = 0; f < 2; f++)
        #pragma unroll
        for (int j = 0; j < 8; j++)
            #pragma unroll
            for (int q = 0; q < 4; q++) c[f][j][q] = 0.f;

    auto prefetch = [&](int kc, int buf) {
        int k0 = kc * 32;
        uint32_t bA = sb_u32 + (uint32_t)(buf * BUF_FLOATS) * 4u;
        uint32_t bB = bA + (uint32_t)A_FLOATS * 4u;
        // B: 128n x 32k = 1024 float4 -> 8 per thread
        #pragma unroll
        for (int i = 0; i < 8; i++) {
            int idx = i * 128 + tid;
            int n  = idx >> 3;
            int c4 = (idx & 7) * 4;
            CP16(bB + (uint32_t)(n * APITCH + c4) * 4u,
                 WT + (size_t)n * HD + k0 + c4);
        }
        // A: 64 rows x 32k = 512 float4 -> 4 per thread
        if (around) {
            float* smA = sm + buf * BUF_FLOATS;
            #pragma unroll
            for (int i = 0; i < 4; i++) {
                int idx = i * 128 + tid;
                int row = idx >> 3;
                int c4  = (idx & 7) * 4;
                float4 a = make_float4(0.f, 0.f, 0.f, 0.f);
                int gr = base + row;
                if (gr < M) a = *(const float4*)(A + (size_t)gr * HD + k0 + c4);
                a.x = tf32_rna(a.x); a.y = tf32_rna(a.y);
                a.z = tf32_rna(a.z); a.w = tf32_rna(a.w);
                *(float4*)(smA + row * APITCH + c4) = a;
            }
        } else {
            #pragma unroll
            for (int i = 0; i < 4; i++) {
                int idx = i * 128 + tid;
                int row = idx >> 3;
                int c4  = (idx & 7) * 4;
                int gr  = base + row;
                int grc = (gr < M) ? gr : (M - 1);
                unsigned nb = (gr < M) ? 16u : 0u;
                CP16P(bA + (uint32_t)(row * APITCH + c4) * 4u,
                      A + (size_t)grc * HD + k0 + c4, nb);
            }
        }
    };

    prefetch(0, 0); CP_COMMIT();
    prefetch(1, 1); CP_COMMIT();

    for (int kc = 0; kc < 4; kc++) {
        if (kc < 3) { CP_WAIT1(); } else { CP_WAIT0(); }
        __syncthreads();

        const float* smA = sm + (kc & 1) * BUF_FLOATS;
        const float* smB = smA + A_FLOATS;
        #pragma unroll
        for (int ks = 0; ks < 4; ks++) {
            int k = ks * 8;
            uint32_t af[2][4];
            #pragma unroll
            for (int f = 0; f < 2; f++) {
                int r0 = (wm * 32 + f * 16 + g) * APITCH + k + tig;
                int r1 = (wm * 32 + f * 16 + 8 + g) * APITCH + k + tig;
                af[f][0] = __float_as_uint(smA[r0]);
                af[f][1] = __float_as_uint(smA[r1]);
                af[f][2] = __float_as_uint(smA[r0 + 4]);
                af[f][3] = __float_as_uint(smA[r1 + 4]);
            }
            #pragma unroll
            for (int j = 0; j < 8; j++) {
                int nb = (wn * 64 + j * 8 + g) * APITCH + k + tig;
                uint32_t bf[2];
                bf[0] = __float_as_uint(smB[nb]);
                bf[1] = __float_as_uint(smB[nb + 4]);
                mma_tf32(c[0][j], af[0], bf);
                mma_tf32(c[1][j], af[1], bf);
            }
        }
        __syncthreads();
        if (kc + 2 < 4) { prefetch(kc + 2, kc & 1); CP_COMMIT(); }
    }

    // epilogue
    #pragma unroll
    for (int f = 0; f < 2; f++) {
        int r0 = base + wm * 32 + f * 16 + g;
        int r1 = r0 + 8;
        float d0 = 1.f, d1 = 1.f;
        if (scale) {
            if (r0 < M) d0 = g_dinv[r0];
            if (r1 < M) d1 = g_dinv[r1];
        }
        #pragma unroll
        for (int j = 0; j < 8; j++) {
            int col = wn * 64 + j * 8 + 2 * tig;
            if (r0 < M)
                *(float2*)(C + (size_t)r0 * HD + col) =
                    make_float2(c[f][j][0] * d0, c[f][j][1] * d0);
            if (r1 < M)
                *(float2*)(C + (size_t)r1 * HD + col) =
                    make_float2(c[f][j][2] * d1, c[f][j][3] * d1);
        }
    }
}

// ---------------- aggregation; optional self-scale and tf32 pre-round ------
__global__ __launch_bounds__(256) void k_agg(const float* __restrict__ z,
                                             const float* __restrict__ bias,
                                             float* __restrict__ out,
                                             int relu, int scale_self, int rnd) {
    int wid  = (blockIdx.x * blockDim.x + threadIdx.x) >> 5;
    int lane = threadIdx.x & 31;
    if (wid >= NN) return;
    const float4* z4 = (const float4*)z;
    float dv = g_dinv[wid];
    float4 acc = z4[(size_t)wid * 32 + lane];
    if (scale_self) { acc.x *= dv; acc.y *= dv; acc.z *= dv; acc.w *= dv; }
    int beg = g_rowptr[wid];
    int end = g_rowptr[wid + 1];
    int j = beg;
    if (scale_self) {
        for (; j + 1 < end; j += 2) {
            int u0 = g_col[j], u1 = g_col[j + 1];
            float d0 = g_dinv[u0], d1 = g_dinv[u1];
            float4 a = z4[(size_t)u0 * 32 + lane];
            float4 b = z4[(size_t)u1 * 32 + lane];
            acc.x = fmaf(d0, a.x, acc.x); acc.y = fmaf(d0, a.y, acc.y);
            acc.z = fmaf(d0, a.z, acc.z); acc.w = fmaf(d0, a.w, acc.w);
            acc.x = fmaf(d1, b.x, acc.x); acc.y = fmaf(d1, b.y, acc.y);
            acc.z = fmaf(d1, b.z, acc.z); acc.w = fmaf(d1, b.w, acc.w);
        }
        for (; j < end; j++) {
            int u = g_col[j];
            float du = g_dinv[u];
            float4 a = z4[(size_t)u * 32 + lane];
            acc.x = fmaf(du, a.x, acc.x); acc.y = fmaf(du, a.y, acc.y);
            acc.z = fmaf(du, a.z, acc.z); acc.w = fmaf(du, a.w, acc.w);
        }
    } else {
        for (; j + 3 < end; j += 4) {
            int u0 = g_col[j], u1 = g_col[j + 1], u2 = g_col[j + 2], u3 = g_col[j + 3];
            float4 a = z4[(size_t)u0 * 32 + lane];
            float4 b = z4[(size_t)u1 * 32 + lane];
            float4 c = z4[(size_t)u2 * 32 + lane];
            float4 d = z4[(size_t)u3 * 32 + lane];
            acc.x += (a.x + b.x) + (c.x + d.x);
            acc.y += (a.y + b.y) + (c.y + d.y);
            acc.z += (a.z + b.z) + (c.z + d.z);
            acc.w += (a.w + b.w) + (c.w + d.w);
        }
        for (; j < end; j++) {
            float4 a = z4[(size_t)g_col[j] * 32 + lane];
            acc.x += a.x; acc.y += a.y; acc.z += a.z; acc.w += a.w;
        }
    }
    float4 bb = ((const float4*)bias)[lane];
    float4 r;
    r.x = fmaf(acc.x, dv, bb.x);
    r.y = fmaf(acc.y, dv, bb.y);
    r.z = fmaf(acc.z, dv, bb.z);
    r.w = fmaf(acc.w, dv, bb.w);
    if (relu) {
        r.x = fmaxf(r.x, 0.f); r.y = fmaxf(r.y, 0.f);
        r.z = fmaxf(r.z, 0.f); r.w = fmaxf(r.w, 0.f);
    }
    if (rnd) {
        r.x = tf32_rna(r.x); r.y = tf32_rna(r.y);
        r.z = tf32_rna(r.z); r.w = tf32_rna(r.w);
    }
    ((float4*)out)[(size_t)wid * 32 + lane] = r;
}

// ---------------- mean pool per graph ----------------
__global__ __launch_bounds__(128) void k_pool(const float* __restrict__ h,
                                              const int* __restrict__ batch,
                                              float* __restrict__ dout) {
    int g = blockIdx.x;
    int c = threadIdx.x;
    int lo = 0, hi = NN;
    while (lo < hi) { int m = (lo + hi) >> 1; if (batch[m] < g) lo = m + 1; else hi = m; }
    int start = lo;
    lo = 0; hi = NN;
    while (lo < hi) { int m = (lo + hi) >> 1; if (batch[m] < g + 1) lo = m + 1; else hi = m; }
    int end = lo;
    float s = 0.f;
    for (int v = start; v < end; v++) s += h[(size_t)v * 128 + c];
    float cnt = (float)(end - start);
    float val = s / fmaxf(cnt, 1.0f);
    g_f[g * 128 + c] = val;
    dout[g * 128 + c] = val;
}

// ---------------- MLP layer (round-1 exact) --------------------------------
__global__ __launch_bounds__(256) void k_fc(const float* __restrict__ in,
                                            const float* __restrict__ W,
                                            const float* __restrict__ b,
                                            float* __restrict__ out,
                                            int K, int C, int relu) {
    __shared__ float s_in[1024];
    int g = blockIdx.x;
    for (int k = threadIdx.x; k < K; k += blockDim.x) s_in[k] = in[g * K + k];
    __syncthreads();
    int c = blockIdx.y * blockDim.x + threadIdx.x;
    if (c < C) {
        float acc = b[c];
        for (int k = 0; k < K; k++) acc = fmaf(s_in[k], W[(size_t)k * C + c], acc);
        if (relu) acc = fmaxf(acc, 0.f);
        out[g * C + c] = acc;
    }
}

extern "C" void kernel_launch(void* const* d_in, const int* in_sizes, int n_in,
                              void* d_out, int out_size) {
    const float* x     = (const float*)d_in[0];
    const int*   ei    = (const int*)d_in[1];
    const int*   batch = (const int*)d_in[2];
    const float* c1w = (const float*)d_in[3];
    const float* c1b = (const float*)d_in[4];
    const float* c2w = (const float*)d_in[5];
    const float* c2b = (const float*)d_in[6];
    const float* c3w = (const float*)d_in[7];
    const float* c3b = (const float*)d_in[8];
    const float* f1w = (const float*)d_in[9];
    const float* f1b = (const float*)d_in[10];
    const float* f2w = (const float*)d_in[11];
    const float* f2b = (const float*)d_in[12];
    const float* f3w = (const float*)d_in[13];
    const float* f3b = (const float*)d_in[14];
    const float* f4w = (const float*)d_in[15];
    const float* f4b = (const float*)d_in[16];
    const float* f5w = (const float*)d_in[17];
    const float* f5b = (const float*)d_in[18];
    float* dout = (float*)d_out;

    float *p_z, *p_h, *p_f, *p_t1, *p_t2, *p_t3, *p_t4, *p_wT;
    int* p_degi;
    cudaGetSymbolAddress((void**)&p_z,  g_z);
    cudaGetSymbolAddress((void**)&p_h,  g_h);
    cudaGetSymbolAddress((void**)&p_f,  g_f);
    cudaGetSymbolAddress((void**)&p_t1, g_t1);
    cudaGetSymbolAddress((void**)&p_t2, g_t2);
    cudaGetSymbolAddress((void**)&p_t3, g_t3);
    cudaGetSymbolAddress((void**)&p_t4, g_t4);
    cudaGetSymbolAddress((void**)&p_wT, g_wT);
    cudaGetSymbolAddress((void**)&p_degi, g_degi);

    static cudaStream_t s2 = 0;
    static cudaEvent_t evA = 0, evB = 0;
    static int init_done = 0;
    if (!init_done) {
        cudaStreamCreateWithFlags(&s2, cudaStreamNonBlocking);
        cudaEventCreateWithFlags(&evA, cudaEventDisableTiming);
        cudaEventCreateWithFlags(&evB, cudaEventDisableTiming);
        cudaFuncSetAttribute(k_gemm_mma, cudaFuncAttributeMaxDynamicSharedMemorySize,
                             SM_GEMM_FLOATS * sizeof(float));
        init_done = 1;
    }

    int nb = (NN + 1023) / 1024;
    int gemm_blocks = (NN + 63) / 64;
    int agg_blocks  = (NN * 32 + 255) / 256;
    size_t gsm = SM_GEMM_FLOATS * sizeof(float);

    // fork: CSR build on s2; weight prep + raw conv1 GEMM on main
    cudaEventRecord(evA, 0);
    cudaStreamWaitEvent(s2, evA, 0);
    cudaMemsetAsync(p_degi, 0, NN * sizeof(int), s2);
    k_count<<<(EE + 255) / 256, 256, 0, s2>>>(ei);
    k_scan1<<<nb, 1024, 0, s2>>>();
    k_scan3<<<nb, 1024, 0, s2>>>(nb);
    k_fill<<<(EE + 255) / 256, 256, 0, s2>>>(ei);
    cudaEventRecord(evB, s2);

    k_prep<<<24, 256>>>(c1w, c2w, c3w);
    k_gemm_mma<<<gemm_blocks, 128, gsm>>>(x, p_wT, p_z, NN, 0, 1);  // raw; rna in staging

    cudaStreamWaitEvent(0, evB, 0);                                 // join before agg1

    k_agg<<<agg_blocks, 256>>>(p_z, c1b, p_h, 1, 1, 1);             // h pre-rounded
    k_gemm_mma<<<gemm_blocks, 128, gsm>>>(p_h, p_wT + HD * HD, p_z, NN, 1, 0);
    k_agg<<<agg_blocks, 256>>>(p_z, c2b, p_h, 1, 0, 1);
    k_gemm_mma<<<gemm_blocks, 128, gsm>>>(p_h, p_wT + 2 * HD * HD, p_z, NN, 1, 0);
    k_agg<<<agg_blocks, 256>>>(p_z, c3b, p_h, 0, 0, 0);             // final h unrounded

    k_pool<<<GG, 128>>>(p_h, batch, dout);

    k_fc<<<dim3(GG, (1024 + 255) / 256), 256>>>(p_f,  f1w, f1b, p_t1, 128,  1024, 1);
    k_fc<<<dim3(GG, (512  + 255) / 256), 256>>>(p_t1, f2w, f2b, p_t2, 1024, 512,  1);
    k_fc<<<dim3(GG, (256  + 255) / 256), 256>>>(p_t2, f3w, f3b, p_t3, 512,  256,  1);
    k_fc<<<dim3(GG, (128  + 255) / 256), 256>>>(p_t3, f4w, f4b, p_t4, 256,  128,  1);
    k_fc<<<dim3(GG, 1), 256>>>(p_t4, f5w, f5b, dout + GG * HD, 128, 10, 0);
}

// round 12
// speedup vs baseline: 1.1989x; 1.1989x over previous
#include <cuda_runtime.h>
#include <cuda_fp16.h>
#include <math.h>
#include <stdint.h>

#define NN 50000
#define EE 800000
#define HD 128
#define GG 64

// ---------------- scratch (device globals: allocation-free) ----------------
__device__ __half g_zh[NN * HD];      // GEMM output in fp16 (agg gathers)
__device__ float g_h[NN * HD];
__device__ float g_dinv[NN];
__device__ int   g_degi[NN];
__device__ int   g_rowptr[NN + 1];
__device__ int   g_cursor[NN];
__device__ int   g_col[EE];
__device__ int   g_bsum[64];
__device__ float g_f[GG * HD];
__device__ float g_t1[GG * 1024];
__device__ float g_t2[GG * 512];
__device__ float g_t3[GG * 256];
__device__ float g_t4[GG * HD];
__device__ float g_wT[3 * HD * HD];   // W^T, tf32-rounded

// ---------------- helpers ----------------
__device__ __forceinline__ float tf32_rna(float x) {
    uint32_t r; asm("cvt.rna.tf32.f32 %0, %1;" : "=r"(r) : "f"(x));
    return __uint_as_float(r);
}
__device__ __forceinline__ void mma_tf32(float* c, const uint32_t* a, const uint32_t* b) {
    asm volatile(
        "mma.sync.aligned.m16n8k8.row.col.f32.tf32.tf32.f32 "
        "{%0,%1,%2,%3}, {%4,%5,%6,%7}, {%8,%9}, {%0,%1,%2,%3};"
        : "+f"(c[0]), "+f"(c[1]), "+f"(c[2]), "+f"(c[3])
        : "r"(a[0]), "r"(a[1]), "r"(a[2]), "r"(a[3]), "r"(b[0]), "r"(b[1]));
}
#define CP16(dst_u32, src) \
    asm volatile("cp.async.cg.shared.global [%0], [%1], 16;" :: "r"(dst_u32), "l"(src))
#define CP16P(dst_u32, src, nbytes) \
    asm volatile("cp.async.cg.shared.global [%0], [%1], 16, %2;" :: "r"(dst_u32), "l"(src), "r"(nbytes))
#define CP_COMMIT() asm volatile("cp.async.commit_group;" ::: "memory")
#define CP_WAIT1()  asm volatile("cp.async.wait_group 1;" ::: "memory")
#define CP_WAIT0()  asm volatile("cp.async.wait_group 0;" ::: "memory")

// gather one fp16 row segment (4 halves) as fp32
__device__ __forceinline__ float4 ldz4(const __half* z, int row, int lane) {
    uint2 v = *(const uint2*)(z + (size_t)row * HD + lane * 4);
    float2 f0 = __half22float2(*(__half2*)&v.x);
    float2 f1 = __half22float2(*(__half2*)&v.y);
    return make_float4(f0.x, f0.y, f1.x, f1.y);
}

// ---------------- CSR build ----------------
__global__ void k_count(const int* __restrict__ ei) {
    int e = blockIdx.x * blockDim.x + threadIdx.x;
    if (e < EE) atomicAdd(&g_degi[ei[EE + e]], 1);
}
__global__ void k_scan1() {
    __shared__ int s[1024];
    int t = threadIdx.x;
    int i = blockIdx.x * 1024 + t;
    int v = (i < NN) ? g_degi[i] : 0;
    s[t] = v;
    __syncthreads();
    for (int off = 1; off < 1024; off <<= 1) {
        int x = (t >= off) ? s[t - off] : 0;
        __syncthreads();
        s[t] += x;
        __syncthreads();
    }
    if (i < NN) g_rowptr[i] = s[t] - v;
    if (t == 1023) g_bsum[blockIdx.x] = s[1023];
}
__global__ void k_scan3(int nb) {
    __shared__ int sb[64];
    __shared__ int off_s;
    int t = threadIdx.x;
    if (t < nb) sb[t] = g_bsum[t];
    __syncthreads();
    if (t == 0) {
        int s = 0;
        for (int i = 0; i < blockIdx.x; i++) s += sb[i];
        off_s = s;
    }
    __syncthreads();
    int i = blockIdx.x * 1024 + t;
    if (i < NN) {
        int rp = g_rowptr[i] + off_s;
        g_rowptr[i] = rp;
        g_cursor[i] = rp;
        g_dinv[i]   = rsqrtf((float)(g_degi[i] + 1));
    }
    if (i == 0) g_rowptr[NN] = EE;
}
__global__ void k_fill(const int* __restrict__ ei) {
    int e = blockIdx.x * blockDim.x + threadIdx.x;
    if (e < EE) {
        int src = ei[e];
        int dst = ei[EE + e];
        int p = atomicAdd(&g_cursor[dst], 1);
        g_col[p] = src;
    }
}

// ---- weight prep: WT[n][k] = rna(W[k][n]) ----------------------------------
__global__ __launch_bounds__(256) void k_prep(const float* __restrict__ w1,
                                              const float* __restrict__ w2,
                                              const float* __restrict__ w3) {
    int layer = blockIdx.x >> 3;
    int part  = blockIdx.x & 7;
    const float* W = (layer == 0) ? w1 : ((layer == 1) ? w2 : w3);
    float* o = g_wT + layer * (HD * HD);
    for (int i = 0; i < 8; i++) {
        int idx = part * 2048 + i * 256 + threadIdx.x;
        int k = idx >> 7;
        int n = idx & 127;
        o[n * HD + k] = tf32_rna(W[idx]);
    }
}

// ---------------- tf32 mma GEMM, cp.async double-buffered, fp16 out --------
// A: [M,128] fp32. WT: [128n][128k]. Z: [M,128] fp16.
// Block 128x128, 8 warps (4m x 2n), warp tile 32x64, BK=32, m16n8k8.
#define APITCH 36
#define BUF_FLOATS (2 * 128 * APITCH)
#define SM_GEMM_FLOATS (2 * BUF_FLOATS)

__global__ __launch_bounds__(256, 2) void k_gemm_mma(const float* __restrict__ A,
                                                     const float* __restrict__ WT,
                                                     __half* __restrict__ Z,
                                                     int M, int scale, int around) {
    extern __shared__ float sm[];
    uint32_t sb_u32 = (uint32_t)__cvta_generic_to_shared(sm);
    int tid  = threadIdx.x;
    int wid  = tid >> 5;
    int lane = tid & 31;
    int g    = lane >> 2;
    int tig  = lane & 3;
    int wm   = wid & 3;
    int wn   = wid >> 2;
    int base = blockIdx.x * 128;

    float c[2][8][4];
    #pragma unroll
    for (int f = 0; f < 2; f++)
        #pragma unroll
        for (int j = 0; j < 8; j++)
            #pragma unroll
            for (int q = 0; q < 4; q++) c[f][j][q] = 0.f;

    auto prefetch = [&](int kc, int buf) {
        int k0 = kc * 32;
        uint32_t bA = sb_u32 + (uint32_t)(buf * BUF_FLOATS) * 4u;
        uint32_t bB = bA + (uint32_t)(128 * APITCH) * 4u;
        #pragma unroll
        for (int i = 0; i < 4; i++) {
            int idx = i * 256 + tid;
            int n  = idx >> 3;
            int c4 = (idx & 7) * 4;
            CP16(bB + (uint32_t)(n * APITCH + c4) * 4u,
                 WT + (size_t)n * HD + k0 + c4);
        }
        if (around) {
            float* smA = sm + buf * BUF_FLOATS;
            #pragma unroll
            for (int i = 0; i < 4; i++) {
                int idx = i * 256 + tid;
                int row = idx >> 3;
                int c4  = (idx & 7) * 4;
                float4 a = make_float4(0.f, 0.f, 0.f, 0.f);
                int gr = base + row;
                if (gr < M) a = *(const float4*)(A + (size_t)gr * HD + k0 + c4);
                a.x = tf32_rna(a.x); a.y = tf32_rna(a.y);
                a.z = tf32_rna(a.z); a.w = tf32_rna(a.w);
                *(float4*)(smA + row * APITCH + c4) = a;
            }
        } else {
            #pragma unroll
            for (int i = 0; i < 4; i++) {
                int idx = i * 256 + tid;
                int row = idx >> 3;
                int c4  = (idx & 7) * 4;
                int gr  = base + row;
                int grc = (gr < M) ? gr : (M - 1);
                unsigned nb = (gr < M) ? 16u : 0u;
                CP16P(bA + (uint32_t)(row * APITCH + c4) * 4u,
                      A + (size_t)grc * HD + k0 + c4, nb);
            }
        }
    };

    prefetch(0, 0); CP_COMMIT();
    prefetch(1, 1); CP_COMMIT();

    for (int kc = 0; kc < 4; kc++) {
        if (kc < 3) { CP_WAIT1(); } else { CP_WAIT0(); }
        __syncthreads();

        const float* smA = sm + (kc & 1) * BUF_FLOATS;
        const float* smB = smA + 128 * APITCH;
        #pragma unroll
        for (int ks = 0; ks < 4; ks++) {
            int k = ks * 8;
            uint32_t af[2][4];
            #pragma unroll
            for (int f = 0; f < 2; f++) {
                int r0 = (wm * 32 + f * 16 + g) * APITCH + k + tig;
                int r1 = (wm * 32 + f * 16 + 8 + g) * APITCH + k + tig;
                af[f][0] = __float_as_uint(smA[r0]);
                af[f][1] = __float_as_uint(smA[r1]);
                af[f][2] = __float_as_uint(smA[r0 + 4]);
                af[f][3] = __float_as_uint(smA[r1 + 4]);
            }
            #pragma unroll
            for (int j = 0; j < 8; j++) {
                int nb = (wn * 64 + j * 8 + g) * APITCH + k + tig;
                uint32_t bf[2];
                bf[0] = __float_as_uint(smB[nb]);
                bf[1] = __float_as_uint(smB[nb + 4]);
                mma_tf32(c[0][j], af[0], bf);
                mma_tf32(c[1][j], af[1], bf);
            }
        }
        __syncthreads();
        if (kc + 2 < 4) { prefetch(kc + 2, kc & 1); CP_COMMIT(); }
    }

    // epilogue: fp16 stores
    #pragma unroll
    for (int f = 0; f < 2; f++) {
        int r0 = base + wm * 32 + f * 16 + g;
        int r1 = r0 + 8;
        float d0 = 1.f, d1 = 1.f;
        if (scale) {
            if (r0 < M) d0 = g_dinv[r0];
            if (r1 < M) d1 = g_dinv[r1];
        }
        #pragma unroll
        for (int j = 0; j < 8; j++) {
            int col = wn * 64 + j * 8 + 2 * tig;
            if (r0 < M)
                *(__half2*)(Z + (size_t)r0 * HD + col) =
                    __floats2half2_rn(c[f][j][0] * d0, c[f][j][1] * d0);
            if (r1 < M)
                *(__half2*)(Z + (size_t)r1 * HD + col) =
                    __floats2half2_rn(c[f][j][2] * d1, c[f][j][3] * d1);
        }
    }
}

// ---------------- aggregation over fp16 z; fp32 accumulate -----------------
__global__ __launch_bounds__(256) void k_agg(const __half* __restrict__ z,
                                             const float* __restrict__ bias,
                                             float* __restrict__ out,
                                             int relu, int scale_self, int rnd) {
    int wid  = (blockIdx.x * blockDim.x + threadIdx.x) >> 5;
    int lane = threadIdx.x & 31;
    if (wid >= NN) return;
    float dv = g_dinv[wid];
    float4 acc = ldz4(z, wid, lane);
    if (scale_self) { acc.x *= dv; acc.y *= dv; acc.z *= dv; acc.w *= dv; }
    int beg = g_rowptr[wid];
    int end = g_rowptr[wid + 1];
    int j = beg;
    if (scale_self) {
        for (; j + 1 < end; j += 2) {
            int u0 = g_col[j], u1 = g_col[j + 1];
            float d0 = g_dinv[u0], d1 = g_dinv[u1];
            float4 a = ldz4(z, u0, lane);
            float4 b = ldz4(z, u1, lane);
            acc.x = fmaf(d0, a.x, acc.x); acc.y = fmaf(d0, a.y, acc.y);
            acc.z = fmaf(d0, a.z, acc.z); acc.w = fmaf(d0, a.w, acc.w);
            acc.x = fmaf(d1, b.x, acc.x); acc.y = fmaf(d1, b.y, acc.y);
            acc.z = fmaf(d1, b.z, acc.z); acc.w = fmaf(d1, b.w, acc.w);
        }
        for (; j < end; j++) {
            int u = g_col[j];
            float du = g_dinv[u];
            float4 a = ldz4(z, u, lane);
            acc.x = fmaf(du, a.x, acc.x); acc.y = fmaf(du, a.y, acc.y);
            acc.z = fmaf(du, a.z, acc.z); acc.w = fmaf(du, a.w, acc.w);
        }
    } else {
        for (; j + 3 < end; j += 4) {
            int u0 = g_col[j], u1 = g_col[j + 1], u2 = g_col[j + 2], u3 = g_col[j + 3];
            float4 a = ldz4(z, u0, lane);
            float4 b = ldz4(z, u1, lane);
            float4 c = ldz4(z, u2, lane);
            float4 d = ldz4(z, u3, lane);
            acc.x += (a.x + b.x) + (c.x + d.x);
            acc.y += (a.y + b.y) + (c.y + d.y);
            acc.z += (a.z + b.z) + (c.z + d.z);
            acc.w += (a.w + b.w) + (c.w + d.w);
        }
        for (; j < end; j++) {
            float4 a = ldz4(z, g_col[j], lane);
            acc.x += a.x; acc.y += a.y; acc.z += a.z; acc.w += a.w;
        }
    }
    float4 bb = ((const float4*)bias)[lane];
    float4 r;
    r.x = fmaf(acc.x, dv, bb.x);
    r.y = fmaf(acc.y, dv, bb.y);
    r.z = fmaf(acc.z, dv, bb.z);
    r.w = fmaf(acc.w, dv, bb.w);
    if (relu) {
        r.x = fmaxf(r.x, 0.f); r.y = fmaxf(r.y, 0.f);
        r.z = fmaxf(r.z, 0.f); r.w = fmaxf(r.w, 0.f);
    }
    if (rnd) {
        r.x = tf32_rna(r.x); r.y = tf32_rna(r.y);
        r.z = tf32_rna(r.z); r.w = tf32_rna(r.w);
    }
    ((float4*)out)[(size_t)wid * 32 + lane] = r;
}

// ---------------- mean pool per graph ----------------
__global__ __launch_bounds__(128) void k_pool(const float* __restrict__ h,
                                              const int* __restrict__ batch,
                                              float* __restrict__ dout) {
    int g = blockIdx.x;
    int c = threadIdx.x;
    int lo = 0, hi = NN;
    while (lo < hi) { int m = (lo + hi) >> 1; if (batch[m] < g) lo = m + 1; else hi = m; }
    int start = lo;
    lo = 0; hi = NN;
    while (lo < hi) { int m = (lo + hi) >> 1; if (batch[m] < g + 1) lo = m + 1; else hi = m; }
    int end = lo;
    float s = 0.f;
    for (int v = start; v < end; v++) s += h[(size_t)v * 128 + c];
    float cnt = (float)(end - start);
    float val = s / fmaxf(cnt, 1.0f);
    g_f[g * 128 + c] = val;
    dout[g * 128 + c] = val;
}

// ---------------- MLP layer (round-1 exact) --------------------------------
__global__ __launch_bounds__(256) void k_fc(const float* __restrict__ in,
                                            const float* __restrict__ W,
                                            const float* __restrict__ b,
                                            float* __restrict__ out,
                                            int K, int C, int relu) {
    __shared__ float s_in[1024];
    int g = blockIdx.x;
    for (int k = threadIdx.x; k < K; k += blockDim.x) s_in[k] = in[g * K + k];
    __syncthreads();
    int c = blockIdx.y * blockDim.x + threadIdx.x;
    if (c < C) {
        float acc = b[c];
        for (int k = 0; k < K; k++) acc = fmaf(s_in[k], W[(size_t)k * C + c], acc);
        if (relu) acc = fmaxf(acc, 0.f);
        out[g * C + c] = acc;
    }
}

extern "C" void kernel_launch(void* const* d_in, const int* in_sizes, int n_in,
                              void* d_out, int out_size) {
    const float* x     = (const float*)d_in[0];
    const int*   ei    = (const int*)d_in[1];
    const int*   batch = (const int*)d_in[2];
    const float* c1w = (const float*)d_in[3];
    const float* c1b = (const float*)d_in[4];
    const float* c2w = (const float*)d_in[5];
    const float* c2b = (const float*)d_in[6];
    const float* c3w = (const float*)d_in[7];
    const float* c3b = (const float*)d_in[8];
    const float* f1w = (const float*)d_in[9];
    const float* f1b = (const float*)d_in[10];
    const float* f2w = (const float*)d_in[11];
    const float* f2b = (const float*)d_in[12];
    const float* f3w = (const float*)d_in[13];
    const float* f3b = (const float*)d_in[14];
    const float* f4w = (const float*)d_in[15];
    const float* f4b = (const float*)d_in[16];
    const float* f5w = (const float*)d_in[17];
    const float* f5b = (const float*)d_in[18];
    float* dout = (float*)d_out;

    float *p_h, *p_f, *p_t1, *p_t2, *p_t3, *p_t4, *p_wT;
    __half* p_zh;
    int* p_degi;
    cudaGetSymbolAddress((void**)&p_zh, g_zh);
    cudaGetSymbolAddress((void**)&p_h,  g_h);
    cudaGetSymbolAddress((void**)&p_f,  g_f);
    cudaGetSymbolAddress((void**)&p_t1, g_t1);
    cudaGetSymbolAddress((void**)&p_t2, g_t2);
    cudaGetSymbolAddress((void**)&p_t3, g_t3);
    cudaGetSymbolAddress((void**)&p_t4, g_t4);
    cudaGetSymbolAddress((void**)&p_wT, g_wT);
    cudaGetSymbolAddress((void**)&p_degi, g_degi);

    static cudaStream_t s2 = 0;
    static cudaEvent_t evA = 0, evB = 0;
    static int init_done = 0;
    if (!init_done) {
        cudaStreamCreateWithFlags(&s2, cudaStreamNonBlocking);
        cudaEventCreateWithFlags(&evA, cudaEventDisableTiming);
        cudaEventCreateWithFlags(&evB, cudaEventDisableTiming);
        cudaFuncSetAttribute(k_gemm_mma, cudaFuncAttributeMaxDynamicSharedMemorySize,
                             SM_GEMM_FLOATS * sizeof(float));
        init_done = 1;
    }

    int nb = (NN + 1023) / 1024;
    int gemm_blocks = (NN + 127) / 128;
    int agg_blocks  = (NN * 32 + 255) / 256;
    size_t gsm = SM_GEMM_FLOATS * sizeof(float);

    // fork: CSR build on s2; weight prep + raw conv1 GEMM on main
    cudaEventRecord(evA, 0);
    cudaStreamWaitEvent(s2, evA, 0);
    cudaMemsetAsync(p_degi, 0, NN * sizeof(int), s2);
    k_count<<<(EE + 255) / 256, 256, 0, s2>>>(ei);
    k_scan1<<<nb, 1024, 0, s2>>>();
    k_scan3<<<nb, 1024, 0, s2>>>(nb);
    k_fill<<<(EE + 255) / 256, 256, 0, s2>>>(ei);
    cudaEventRecord(evB, s2);

    k_prep<<<24, 256>>>(c1w, c2w, c3w);
    k_gemm_mma<<<gemm_blocks, 256, gsm>>>(x, p_wT, p_zh, NN, 0, 1);

    cudaStreamWaitEvent(0, evB, 0);

    k_agg<<<agg_blocks, 256>>>(p_zh, c1b, p_h, 1, 1, 1);
    k_gemm_mma<<<gemm_blocks, 256, gsm>>>(p_h, p_wT + HD * HD, p_zh, NN, 1, 0);
    k_agg<<<agg_blocks, 256>>>(p_zh, c2b, p_h, 1, 0, 1);
    k_gemm_mma<<<gemm_blocks, 256, gsm>>>(p_h, p_wT + 2 * HD * HD, p_zh, NN, 1, 0);
    k_agg<<<agg_blocks, 256>>>(p_zh, c3b, p_h, 0, 0, 0);

    k_pool<<<GG, 128>>>(p_h, batch, dout);

    k_fc<<<dim3(GG, (1024 + 255) / 256), 256>>>(p_f,  f1w, f1b, p_t1, 128,  1024, 1);
    k_fc<<<dim3(GG, (512  + 255) / 256), 256>>>(p_t1, f2w, f2b, p_t2, 1024, 512,  1);
    k_fc<<<dim3(GG, (256  + 255) / 256), 256>>>(p_t2, f3w, f3b, p_t3, 512,  256,  1);
    k_fc<<<dim3(GG, (128  + 255) / 256), 256>>>(p_t3, f4w, f4b, p_t4, 256,  128,  1);
    k_fc<<<dim3(GG, 1), 256>>>(p_t4, f5w, f5b, dout + GG * HD, 128, 10, 0);
}